// round 7
// baseline (speedup 1.0000x reference)
#include <cuda_runtime.h>
#include <cuda_fp16.h>

// Problem constants
#define B  2
#define C  256
#define H  200
#define W  336
#define R  1000
#define OH 14
#define OW 14
#define HW (H * W)           // 67200
#define SCALE 0.25f

// NHWC features in fp16: 2*67200*256*2B = 68.8 MB (kept L2-resident)
__device__ static __half g_feat[(size_t)B * HW * C];

// ---------------------------------------------------------------------------
// Kernel 1: NCHW fp32 -> NHWC fp16 transpose (4x4 register micro-transpose,
// XOR-swizzled smem). Source reads streamed (__ldcs): single use.
// ---------------------------------------------------------------------------
#define TSTRIDE 68
__global__ __launch_bounds__(256) void transpose_kernel(const float* __restrict__ src) {
    __shared__ float tileT[64 * TSTRIDE];

    const int batch = blockIdx.z;
    const int p0 = blockIdx.x * 64;
    const int c0 = blockIdx.y * 64;
    const float* s = src + (size_t)batch * C * HW;
    __half*      d = g_feat + (size_t)batch * HW * C;

    {
        const int tx = threadIdx.x & 15;
        const int ty = threadIdx.x >> 4;
        const float* rb = s + (size_t)(c0 + ty * 4) * HW + p0 + tx * 4;
        const float4 v0 = __ldcs((const float4*)(rb));
        const float4 v1 = __ldcs((const float4*)(rb + HW));
        const float4 v2 = __ldcs((const float4*)(rb + 2 * (size_t)HW));
        const float4 v3 = __ldcs((const float4*)(rb + 3 * (size_t)HW));

        float* wb = &tileT[(4 * tx) * TSTRIDE + 4 * ((ty ^ tx) & 15)];
        *(float4*)(wb + 0 * TSTRIDE) = make_float4(v0.x, v1.x, v2.x, v3.x);
        *(float4*)(wb + 1 * TSTRIDE) = make_float4(v0.y, v1.y, v2.y, v3.y);
        *(float4*)(wb + 2 * TSTRIDE) = make_float4(v0.z, v1.z, v2.z, v3.z);
        *(float4*)(wb + 3 * TSTRIDE) = make_float4(v0.w, v1.w, v2.w, v3.w);
    }
    __syncthreads();

    {
        const int c4 = threadIdx.x & 15;
        const int pr = threadIdx.x >> 4;
        #pragma unroll
        for (int k = 0; k < 4; k++) {
            const int p = pr + k * 16;
            const float4 w = *(const float4*)&tileT[p * TSTRIDE + 4 * ((c4 ^ (p >> 2)) & 15)];
            const __half2 h0 = __floats2half2_rn(w.x, w.y);
            const __half2 h1 = __floats2half2_rn(w.z, w.w);
            uint2 u;
            u.x = *reinterpret_cast<const unsigned int*>(&h0);
            u.y = *reinterpret_cast<const unsigned int*>(&h1);
            *reinterpret_cast<uint2*>(d + (size_t)(p0 + p) * C + c0 + c4 * 4) = u;
        }
    }
}

// ---------------------------------------------------------------------------
// Kernel 2: ROI-align gather. Block = (roi, oh-pair), 448 threads =
// 32 channel-groups (8ch, uint4) x 14 lanes; each lane: exactly 2 samples.
// Both samples' 4 corner loads are issued back-to-back (8 LDG.128 in flight,
// MLP=8) before any blending. 3 blocks/SM (48-reg cap).
// ---------------------------------------------------------------------------
#define CPAD 260

__global__ __launch_bounds__(448, 3) void roi_gather_kernel(
    const float* __restrict__ rois, float* __restrict__ out)
{
    const int blk  = blockIdx.x;
    const int r    = blk / 7;
    const int oh0  = (blk - r * 7) * 2;
    const int t    = threadIdx.x;
    const int cg   = t & 31;    // channel group: channels 8cg..8cg+7
    const int lane = t >> 5;    // 0..13 = ow

    const float bf = __ldg(&rois[r * 5 + 0]);
    const float x1 = __ldg(&rois[r * 5 + 1]);
    const float y1 = __ldg(&rois[r * 5 + 2]);
    const float x2 = __ldg(&rois[r * 5 + 3]);
    const float y2 = __ldg(&rois[r * 5 + 4]);
    const int  b   = (int)bf;

    const uint4* f4 = reinterpret_cast<const uint4*>(g_feat) + (size_t)b * HW * 32;

    __shared__ float sout[28 * CPAD];   // 29.1 KB

    // x-geometry shared by both samples (same ow)
    const float gx  = ((float)lane + 0.5f) * (1.0f / OW);
    const float fx  = (x1 + gx * (x2 - x1)) * SCALE - 0.5f;
    const float x0f = floorf(fx);
    const float lx  = fx - x0f;
    const int   xi0 = (int)x0f;
    const int   xi1 = xi0 + 1;
    const float wx0 = (1.0f - lx) * ((xi0 >= 0 && xi0 < W) ? 1.0f : 0.0f);
    const float wx1 = lx * ((xi1 >= 0 && xi1 < W) ? 1.0f : 0.0f);
    const int   x0c = min(max(xi0, 0), W - 1);
    const int   x1c = min(max(xi1, 0), W - 1);

    // y-geometry for both samples
    float w00[2], w01[2], w10[2], w11[2];
    int   row0[2], row1[2];
    #pragma unroll
    for (int k = 0; k < 2; k++) {
        const float gy  = ((float)(oh0 + k) + 0.5f) * (1.0f / OH);
        const float fy  = (y1 + gy * (y2 - y1)) * SCALE - 0.5f;
        const float y0f = floorf(fy);
        const float ly  = fy - y0f;
        const int   yi0 = (int)y0f;
        const int   yi1 = yi0 + 1;
        const float wy0 = (1.0f - ly) * ((yi0 >= 0 && yi0 < H) ? 1.0f : 0.0f);
        const float wy1 = ly * ((yi1 >= 0 && yi1 < H) ? 1.0f : 0.0f);
        row0[k] = min(max(yi0, 0), H - 1) * W;
        row1[k] = min(max(yi1, 0), H - 1) * W;
        w00[k] = wy0 * wx0; w01[k] = wy0 * wx1;
        w10[k] = wy1 * wx0; w11[k] = wy1 * wx1;
    }

    // Issue all 8 corner loads back-to-back (MLP=8)
    const uint4 a00 = __ldg(&f4[(size_t)(row0[0] + x0c) * 32 + cg]);
    const uint4 a01 = __ldg(&f4[(size_t)(row0[0] + x1c) * 32 + cg]);
    const uint4 a10 = __ldg(&f4[(size_t)(row1[0] + x0c) * 32 + cg]);
    const uint4 a11 = __ldg(&f4[(size_t)(row1[0] + x1c) * 32 + cg]);
    const uint4 b00 = __ldg(&f4[(size_t)(row0[1] + x0c) * 32 + cg]);
    const uint4 b01 = __ldg(&f4[(size_t)(row0[1] + x1c) * 32 + cg]);
    const uint4 b10 = __ldg(&f4[(size_t)(row1[1] + x0c) * 32 + cg]);
    const uint4 b11 = __ldg(&f4[(size_t)(row1[1] + x1c) * 32 + cg]);

    #define BLEND(U00, U01, U10, U11, K, CMP, OA, OB)                                   \
        {                                                                               \
            const float2 ca = __half22float2(*reinterpret_cast<const __half2*>(&U00.CMP)); \
            const float2 cb = __half22float2(*reinterpret_cast<const __half2*>(&U01.CMP)); \
            const float2 cc = __half22float2(*reinterpret_cast<const __half2*>(&U10.CMP)); \
            const float2 cd = __half22float2(*reinterpret_cast<const __half2*>(&U11.CMP)); \
            OA = fmaf(w00[K], ca.x, fmaf(w01[K], cb.x, fmaf(w10[K], cc.x, w11[K] * cd.x))); \
            OB = fmaf(w00[K], ca.y, fmaf(w01[K], cb.y, fmaf(w10[K], cc.y, w11[K] * cd.y))); \
        }

    {   // sample k=0
        float o0, o1, o2, o3, o4, o5, o6, o7;
        BLEND(a00, a01, a10, a11, 0, x, o0, o1)
        BLEND(a00, a01, a10, a11, 0, y, o2, o3)
        BLEND(a00, a01, a10, a11, 0, z, o4, o5)
        BLEND(a00, a01, a10, a11, 0, w, o6, o7)
        float* sb = &sout[lane * CPAD];
        *(float4*)(sb + cg * 4)       = make_float4(o0, o1, o2, o3);
        *(float4*)(sb + 128 + cg * 4) = make_float4(o4, o5, o6, o7);
    }
    {   // sample k=1
        float o0, o1, o2, o3, o4, o5, o6, o7;
        BLEND(b00, b01, b10, b11, 1, x, o0, o1)
        BLEND(b00, b01, b10, b11, 1, y, o2, o3)
        BLEND(b00, b01, b10, b11, 1, z, o4, o5)
        BLEND(b00, b01, b10, b11, 1, w, o6, o7)
        float* sb = &sout[(lane + 14) * CPAD];
        *(float4*)(sb + cg * 4)       = make_float4(o0, o1, o2, o3);
        *(float4*)(sb + 128 + cg * 4) = make_float4(o4, o5, o6, o7);
    }
    #undef BLEND
    __syncthreads();

    // Writeback: 1792 units = 64 channel-quads x 28 samples; 4 per thread.
    float* obase = out + (size_t)r * C * (OH * OW) + oh0 * OW;
    #pragma unroll
    for (int k = 0; k < 4; k++) {
        const int i4 = t + k * 448;
        const int q  = i4 / 28;          // 0..63
        const int jj = i4 - q * 28;      // 0..27
        const int off4 = ((q & 1) << 7) + ((q >> 1) << 2);
        const float4 w = *(const float4*)&sout[jj * CPAD + off4];
        float* ob = obase + (size_t)(q * 4) * (OH * OW) + jj;
        __stcs(ob,                 w.x);
        __stcs(ob +     (OH * OW), w.y);
        __stcs(ob + 2 * (OH * OW), w.z);
        __stcs(ob + 3 * (OH * OW), w.w);
    }
}

// ---------------------------------------------------------------------------
extern "C" void kernel_launch(void* const* d_in, const int* in_sizes, int n_in,
                              void* d_out, int out_size) {
    const float* features = (const float*)d_in[0];
    const float* rois     = (const float*)d_in[1];
    if (n_in >= 2 && in_sizes[0] == R * 5) {
        features = (const float*)d_in[1];
        rois     = (const float*)d_in[0];
    }
    float* out = (float*)d_out;

    dim3 tgrid(HW / 64, C / 64, B);   // (1050, 4, 2)
    transpose_kernel<<<tgrid, 256>>>(features);

    roi_gather_kernel<<<R * 7, 448>>>(rois, out);
}